// round 1
// baseline (speedup 1.0000x reference)
#include <cuda_runtime.h>
#include <math.h>

#define B_ 2
#define S_ 2048
#define E_ 1024
#define H_ 16
#define D_ 64

// Scratch (allocation-free rule: __device__ globals)
__device__ float g_qkv[(size_t)B_ * S_ * 3 * E_];  // [B*S][3*E], col = c*1024 + h*64 + d
__device__ float g_att[(size_t)B_ * S_ * E_];      // [B*S][E],   col = h*64 + d

// ---------------------------------------------------------------------------
// GEMM: C[m][n] = sum_k A[m][k] * B[n][k] + bias[n]
// A: [M,K] row-major, B: [N,K] row-major. M%128==0, N%128==0, K%16==0.
// 128x128 tile, BK=16, 256 threads, 8x8 per thread (strided by 16).
// ---------------------------------------------------------------------------
__global__ __launch_bounds__(256) void gemm_nt_bias(
    const float* __restrict__ A, const float* __restrict__ Bm,
    const float* __restrict__ bias, float* __restrict__ C,
    int M, int N, int K)
{
    __shared__ float As[16][129];
    __shared__ float Bs[16][129];

    const int tid = threadIdx.x;
    const int m0 = blockIdx.y * 128;
    const int n0 = blockIdx.x * 128;
    const int ty = tid >> 4;   // 0..15
    const int tx = tid & 15;   // 0..15

    float acc[8][8];
#pragma unroll
    for (int i = 0; i < 8; ++i)
#pragma unroll
        for (int j = 0; j < 8; ++j) acc[i][j] = 0.f;

    for (int k0 = 0; k0 < K; k0 += 16) {
        // Load 128x16 tiles of A and B, transposed into smem. 512 float4 each.
#pragma unroll
        for (int t = 0; t < 2; ++t) {
            int idx = tid + t * 256;           // 0..511
            int row = idx >> 2;                // 0..127
            int vec = idx & 3;                 // 0..3
            float4 va = *(const float4*)(A + (size_t)(m0 + row) * K + k0 + vec * 4);
            As[vec * 4 + 0][row] = va.x;
            As[vec * 4 + 1][row] = va.y;
            As[vec * 4 + 2][row] = va.z;
            As[vec * 4 + 3][row] = va.w;
            float4 vb = *(const float4*)(Bm + (size_t)(n0 + row) * K + k0 + vec * 4);
            Bs[vec * 4 + 0][row] = vb.x;
            Bs[vec * 4 + 1][row] = vb.y;
            Bs[vec * 4 + 2][row] = vb.z;
            Bs[vec * 4 + 3][row] = vb.w;
        }
        __syncthreads();

#pragma unroll
        for (int kk = 0; kk < 16; ++kk) {
            float a[8], b[8];
#pragma unroll
            for (int i = 0; i < 8; ++i) a[i] = As[kk][ty + 16 * i];
#pragma unroll
            for (int j = 0; j < 8; ++j) b[j] = Bs[kk][tx + 16 * j];
#pragma unroll
            for (int i = 0; i < 8; ++i)
#pragma unroll
                for (int j = 0; j < 8; ++j)
                    acc[i][j] = fmaf(a[i], b[j], acc[i][j]);
        }
        __syncthreads();
    }

#pragma unroll
    for (int j = 0; j < 8; ++j) {
        float bv = bias[n0 + tx + 16 * j];
#pragma unroll
        for (int i = 0; i < 8; ++i) {
            C[(size_t)(m0 + ty + 16 * i) * N + n0 + tx + 16 * j] = acc[i][j] + bv;
        }
    }
}

// ---------------------------------------------------------------------------
// Flash attention: per block = 128 queries of one (b, h). 64-key tiles,
// online softmax (fp32), mask-aware, writes [b, s, h*64+d] layout to g_att.
// ---------------------------------------------------------------------------
#define FA_SMEM_FLOATS (2 * 128 * 65 + 2 * 64 * 65 + 3 * 128 + 64)
#define FA_SMEM_BYTES (FA_SMEM_FLOATS * 4)

__global__ __launch_bounds__(256) void flash_attn(const int* __restrict__ mask)
{
    extern __shared__ float smraw[];
    float (*Qs)[65] = (float(*)[65])smraw;                       // 128 x 65
    float (*Ss)[65] = (float(*)[65])(smraw + 128 * 65);          // 128 x 65
    float (*Ks)[65] = (float(*)[65])(smraw + 2 * 128 * 65);      // 64 x 65
    float (*Vs)[65] = (float(*)[65])(smraw + 2 * 128 * 65 + 64 * 65);
    float* mrow = smraw + 2 * 128 * 65 + 2 * 64 * 65;            // 128
    float* lrow = mrow + 128;                                    // 128
    float* arow = lrow + 128;                                    // 128
    int* maskS  = (int*)(arow + 128);                            // 64

    const int tid = threadIdx.x;
    const int q0 = blockIdx.x * 128;
    const int h  = blockIdx.y;
    const int b  = blockIdx.z;
    const int ty = tid >> 4;   // 0..15
    const int tx = tid & 15;   // 0..15

    const size_t rowstride = (size_t)3 * E_;
    const float* qbase = g_qkv + (size_t)(b * S_ + q0) * rowstride + h * D_;

    // Load Q tile (pre-scaled by 1/sqrt(D))
    for (int idx = tid; idx < 128 * 16; idx += 256) {
        int row = idx >> 4;
        int vec = idx & 15;
        float4 v = *(const float4*)(qbase + (size_t)row * rowstride + vec * 4);
        Qs[row][vec * 4 + 0] = v.x * 0.125f;
        Qs[row][vec * 4 + 1] = v.y * 0.125f;
        Qs[row][vec * 4 + 2] = v.z * 0.125f;
        Qs[row][vec * 4 + 3] = v.w * 0.125f;
    }
    if (tid < 128) { mrow[tid] = -INFINITY; lrow[tid] = 0.f; }

    float o[8][4];
#pragma unroll
    for (int i = 0; i < 8; ++i)
#pragma unroll
        for (int d = 0; d < 4; ++d) o[i][d] = 0.f;

    __syncthreads();

    for (int k0 = 0; k0 < S_; k0 += 64) {
        // Load K, V tiles (64 x 64) + mask
        const float* kb = g_qkv + (size_t)(b * S_ + k0) * rowstride + E_ + h * D_;
        for (int idx = tid; idx < 64 * 16; idx += 256) {
            int row = idx >> 4;
            int vec = idx & 15;
            float4 kv = *(const float4*)(kb + (size_t)row * rowstride + vec * 4);
            Ks[row][vec * 4 + 0] = kv.x;
            Ks[row][vec * 4 + 1] = kv.y;
            Ks[row][vec * 4 + 2] = kv.z;
            Ks[row][vec * 4 + 3] = kv.w;
            float4 vv = *(const float4*)(kb + E_ + (size_t)row * rowstride + vec * 4);
            Vs[row][vec * 4 + 0] = vv.x;
            Vs[row][vec * 4 + 1] = vv.y;
            Vs[row][vec * 4 + 2] = vv.z;
            Vs[row][vec * 4 + 3] = vv.w;
        }
        if (tid < 64) maskS[tid] = mask[b * S_ + k0 + tid];
        __syncthreads();

        // S = Q K^T  (Q already scaled)
        float s[8][4];
#pragma unroll
        for (int i = 0; i < 8; ++i)
#pragma unroll
            for (int j = 0; j < 4; ++j) s[i][j] = 0.f;

#pragma unroll 16
        for (int d = 0; d < 64; ++d) {
            float qv[8], kv[4];
#pragma unroll
            for (int i = 0; i < 8; ++i) qv[i] = Qs[ty + 16 * i][d];
#pragma unroll
            for (int j = 0; j < 4; ++j) kv[j] = Ks[tx + 16 * j][d];
#pragma unroll
            for (int i = 0; i < 8; ++i)
#pragma unroll
                for (int j = 0; j < 4; ++j)
                    s[i][j] = fmaf(qv[i], kv[j], s[i][j]);
        }
#pragma unroll
        for (int i = 0; i < 8; ++i)
#pragma unroll
            for (int j = 0; j < 4; ++j)
                Ss[ty + 16 * i][tx + 16 * j] = s[i][j];
        __syncthreads();

        // Online softmax row pass (one thread per query row)
        if (tid < 128) {
            int r = tid;
            float mprev = mrow[r];
            float mnew = mprev;
            for (int c = 0; c < 64; ++c)
                if (maskS[c]) mnew = fmaxf(mnew, Ss[r][c]);
            float alpha = 1.f;
            if (mnew != -INFINITY) alpha = __expf(mprev - mnew); // mprev=-inf -> 0
            float lsum = 0.f;
            for (int c = 0; c < 64; ++c) {
                float p = 0.f;
                if (maskS[c]) p = __expf(Ss[r][c] - mnew);
                Ss[r][c] = p;
                lsum += p;
            }
            lrow[r] = lrow[r] * alpha + lsum;
            mrow[r] = mnew;
            arow[r] = alpha;
        }
        __syncthreads();

        // O = O * alpha + P @ V
        float al[8];
#pragma unroll
        for (int i = 0; i < 8; ++i) al[i] = arow[ty + 16 * i];
#pragma unroll
        for (int i = 0; i < 8; ++i)
#pragma unroll
            for (int d = 0; d < 4; ++d) o[i][d] *= al[i];

#pragma unroll 16
        for (int j = 0; j < 64; ++j) {
            float pv[8], vv[4];
#pragma unroll
            for (int i = 0; i < 8; ++i) pv[i] = Ss[ty + 16 * i][j];
#pragma unroll
            for (int d = 0; d < 4; ++d) vv[d] = Vs[j][tx + 16 * d];
#pragma unroll
            for (int i = 0; i < 8; ++i)
#pragma unroll
                for (int d = 0; d < 4; ++d)
                    o[i][d] = fmaf(pv[i], vv[d], o[i][d]);
        }
        __syncthreads();   // protect Ks/Vs/Ss before next tile load
    }

    // Normalize and write out (nan_to_num: fully-masked row -> 0)
#pragma unroll
    for (int i = 0; i < 8; ++i) {
        int r = ty + 16 * i;
        float l = lrow[r];
        float inv = (l > 0.f) ? (1.f / l) : 0.f;
#pragma unroll
        for (int d = 0; d < 4; ++d) {
            g_att[(size_t)(b * S_ + q0 + r) * E_ + h * D_ + tx + 16 * d] = o[i][d] * inv;
        }
    }
}

// ---------------------------------------------------------------------------
extern "C" void kernel_launch(void* const* d_in, const int* in_sizes, int n_in,
                              void* d_out, int out_size)
{
    const float* x      = (const float*)d_in[0];
    const int*   mask   = (const int*)d_in[1];
    const float* qkv_w  = (const float*)d_in[2];
    const float* qkv_b  = (const float*)d_in[3];
    const float* proj_w = (const float*)d_in[4];
    const float* proj_b = (const float*)d_in[5];
    float* out = (float*)d_out;

    float *qkv_p, *att_p;
    cudaGetSymbolAddress((void**)&qkv_p, g_qkv);
    cudaGetSymbolAddress((void**)&att_p, g_att);

    // 1) QKV GEMM: [4096,1024] x [3072,1024]^T -> [4096,3072]
    gemm_nt_bias<<<dim3(3 * E_ / 128, B_ * S_ / 128), 256>>>(
        x, qkv_w, qkv_b, qkv_p, B_ * S_, 3 * E_, E_);

    // 2) Flash attention -> g_att [4096,1024]
    cudaFuncSetAttribute(flash_attn, cudaFuncAttributeMaxDynamicSharedMemorySize,
                         FA_SMEM_BYTES);
    flash_attn<<<dim3(S_ / 128, H_, B_), 256, FA_SMEM_BYTES>>>(mask);

    // 3) Proj GEMM: [4096,1024] x [1024,1024]^T -> out [4096,1024]
    gemm_nt_bias<<<dim3(E_ / 128, B_ * S_ / 128), 256>>>(
        att_p, proj_w, proj_b, out, B_ * S_, E_, E_);
}

// round 2
// speedup vs baseline: 2.8031x; 2.8031x over previous
#include <cuda_runtime.h>
#include <math.h>

#define B_ 2
#define S_ 2048
#define E_ 1024
#define H_ 16
#define D_ 64

// Scratch (allocation-free rule: __device__ globals)
__device__ float g_qkv[(size_t)B_ * S_ * 3 * E_];  // [B*S][3*E]
__device__ float g_att[(size_t)B_ * S_ * E_];      // [B*S][E]

__device__ __forceinline__ float tf32r(float x) {
    float r;
    asm("cvt.rna.tf32.f32 %0, %1;" : "=f"(r) : "f"(x));
    return r;
}

#define MMA_TF32(d, a, b)                                                     \
    asm volatile(                                                             \
        "mma.sync.aligned.m16n8k8.row.col.f32.tf32.tf32.f32 "                 \
        "{%0,%1,%2,%3},{%4,%5,%6,%7},{%8,%9},{%0,%1,%2,%3};"                  \
        : "+f"((d)[0]), "+f"((d)[1]), "+f"((d)[2]), "+f"((d)[3])              \
        : "r"((a)[0]), "r"((a)[1]), "r"((a)[2]), "r"((a)[3]),                 \
          "r"((b)[0]), "r"((b)[1]))

// ---------------------------------------------------------------------------
// GEMM: C[m][n] = sum_k A[m][k]*B[n][k] + bias[n].  tf32 MMA, fp32 accum.
// 128x128 tile, BK=32, 256 threads = 8 warps (2x4), warp tile 64x32.
// ---------------------------------------------------------------------------
__global__ __launch_bounds__(256, 2) void gemm_nt_bias_tf32(
    const float* __restrict__ A, const float* __restrict__ Bm,
    const float* __restrict__ bias, float* __restrict__ C,
    int M, int N, int K)
{
    __shared__ float As[128][36];
    __shared__ float Bs[128][36];

    const int tid  = threadIdx.x;
    const int warp = tid >> 5;
    const int lane = tid & 31;
    const int m0 = blockIdx.y * 128;
    const int n0 = blockIdx.x * 128;
    const int wm = (warp >> 2) * 64;
    const int wn = (warp & 3) * 32;
    const int r  = lane >> 2;       // 0..7
    const int cq = lane & 3;        // 0..3

    float acc[4][4][4] = {};

    for (int k0 = 0; k0 < K; k0 += 32) {
        // Load 128x32 A and B tiles (tf32-rounded). 1024 float4 total, 4/thread.
#pragma unroll
        for (int t = 0; t < 4; ++t) {
            int idx = tid + t * 256;
            int row = idx >> 3;
            int vec = idx & 7;
            float4 va = *(const float4*)(A + (size_t)(m0 + row) * K + k0 + vec * 4);
            As[row][vec * 4 + 0] = tf32r(va.x);
            As[row][vec * 4 + 1] = tf32r(va.y);
            As[row][vec * 4 + 2] = tf32r(va.z);
            As[row][vec * 4 + 3] = tf32r(va.w);
            float4 vb = *(const float4*)(Bm + (size_t)(n0 + row) * K + k0 + vec * 4);
            Bs[row][vec * 4 + 0] = tf32r(vb.x);
            Bs[row][vec * 4 + 1] = tf32r(vb.y);
            Bs[row][vec * 4 + 2] = tf32r(vb.z);
            Bs[row][vec * 4 + 3] = tf32r(vb.w);
        }
        __syncthreads();

#pragma unroll
        for (int ks = 0; ks < 4; ++ks) {
            const int kk = ks * 8 + cq;
            unsigned a[4][4], b[4][2];
#pragma unroll
            for (int mt = 0; mt < 4; ++mt) {
                int row = wm + mt * 16 + r;
                a[mt][0] = __float_as_uint(As[row][kk]);
                a[mt][1] = __float_as_uint(As[row + 8][kk]);
                a[mt][2] = __float_as_uint(As[row][kk + 4]);
                a[mt][3] = __float_as_uint(As[row + 8][kk + 4]);
            }
#pragma unroll
            for (int nt = 0; nt < 4; ++nt) {
                int col = wn + nt * 8 + r;
                b[nt][0] = __float_as_uint(Bs[col][kk]);
                b[nt][1] = __float_as_uint(Bs[col][kk + 4]);
            }
#pragma unroll
            for (int mt = 0; mt < 4; ++mt)
#pragma unroll
                for (int nt = 0; nt < 4; ++nt)
                    MMA_TF32(acc[mt][nt], a[mt], b[nt]);
        }
        __syncthreads();
    }

    // Epilogue: bias + store (float2 per row pair)
    const int c2 = cq * 2;
#pragma unroll
    for (int nt = 0; nt < 4; ++nt) {
        int col = n0 + wn + nt * 8 + c2;
        float b0 = bias[col], b1 = bias[col + 1];
#pragma unroll
        for (int mt = 0; mt < 4; ++mt) {
            int row = m0 + wm + mt * 16 + r;
            float2 v0 = make_float2(acc[mt][nt][0] + b0, acc[mt][nt][1] + b1);
            float2 v1 = make_float2(acc[mt][nt][2] + b0, acc[mt][nt][3] + b1);
            *(float2*)(C + (size_t)row * N + col) = v0;
            *(float2*)(C + (size_t)(row + 8) * N + col) = v1;
        }
    }
}

// ---------------------------------------------------------------------------
// Flash attention, tf32 MMA for S=QK^T and O=PV. 128 queries x 64-key tiles.
// ---------------------------------------------------------------------------
#define QS_STRIDE 68
#define FA_WORDS (128 * QS_STRIDE * 2 + 64 * QS_STRIDE * 2 + 3 * 128 + 64)
#define FA_SMEM_BYTES (FA_WORDS * 4)

__global__ __launch_bounds__(256, 2) void flash_attn_tf32(const int* __restrict__ mask)
{
    extern __shared__ float sm[];
    float (*Qs)[QS_STRIDE] = (float(*)[QS_STRIDE])sm;                                   // 128
    float (*Ss)[QS_STRIDE] = (float(*)[QS_STRIDE])(sm + 128 * QS_STRIDE);               // 128
    float (*Ks)[QS_STRIDE] = (float(*)[QS_STRIDE])(sm + 2 * 128 * QS_STRIDE);           // 64
    float (*Vs)[QS_STRIDE] = (float(*)[QS_STRIDE])(sm + 2 * 128 * QS_STRIDE + 64 * QS_STRIDE); // 64
    float* mrow = sm + 2 * 128 * QS_STRIDE + 2 * 64 * QS_STRIDE;  // 128
    float* lrow = mrow + 128;
    float* arow = lrow + 128;
    int*   maskS = (int*)(arow + 128);                            // 64

    const int tid  = threadIdx.x;
    const int warp = tid >> 5;
    const int lane = tid & 31;
    const int q0 = blockIdx.x * 128;
    const int h  = blockIdx.y;
    const int b  = blockIdx.z;
    const int wq = (warp >> 2) * 64;       // query offset of warp
    const int wn = (warp & 3) * 16;        // key/dim offset of warp
    const int r  = lane >> 2;
    const int cq = lane & 3;

    const size_t rowstride = (size_t)3 * E_;
    const float* qbase = g_qkv + (size_t)(b * S_ + q0) * rowstride + h * D_;

    // Load Q tile (scaled by 1/8, tf32-rounded)
#pragma unroll
    for (int t = 0; t < 8; ++t) {
        int idx = tid + t * 256;          // 0..2047
        int row = idx >> 4;
        int vec = idx & 15;
        float4 v = *(const float4*)(qbase + (size_t)row * rowstride + vec * 4);
        Qs[row][vec * 4 + 0] = tf32r(v.x * 0.125f);
        Qs[row][vec * 4 + 1] = tf32r(v.y * 0.125f);
        Qs[row][vec * 4 + 2] = tf32r(v.z * 0.125f);
        Qs[row][vec * 4 + 3] = tf32r(v.w * 0.125f);
    }
    if (tid < 128) { mrow[tid] = -INFINITY; lrow[tid] = 0.f; }

    float o[4][2][4] = {};
    __syncthreads();

    for (int k0 = 0; k0 < S_; k0 += 64) {
        // Load K, V tiles (64 x 64) + mask slice
        const float* kb = g_qkv + (size_t)(b * S_ + k0) * rowstride + E_ + h * D_;
#pragma unroll
        for (int t = 0; t < 4; ++t) {
            int idx = tid + t * 256;
            int row = idx >> 4;
            int vec = idx & 15;
            float4 kv = *(const float4*)(kb + (size_t)row * rowstride + vec * 4);
            Ks[row][vec * 4 + 0] = tf32r(kv.x);
            Ks[row][vec * 4 + 1] = tf32r(kv.y);
            Ks[row][vec * 4 + 2] = tf32r(kv.z);
            Ks[row][vec * 4 + 3] = tf32r(kv.w);
            float4 vv = *(const float4*)(kb + E_ + (size_t)row * rowstride + vec * 4);
            Vs[row][vec * 4 + 0] = tf32r(vv.x);
            Vs[row][vec * 4 + 1] = tf32r(vv.y);
            Vs[row][vec * 4 + 2] = tf32r(vv.z);
            Vs[row][vec * 4 + 3] = tf32r(vv.w);
        }
        if (tid < 64) maskS[tid] = mask[b * S_ + k0 + tid];
        __syncthreads();

        // ---- S = Q K^T  (warp covers 64q x 16k) ----
        float s[4][2][4] = {};
#pragma unroll
        for (int ks = 0; ks < 8; ++ks) {
            const int kk = ks * 8 + cq;
            unsigned a[4][4], bb[2][2];
#pragma unroll
            for (int mt = 0; mt < 4; ++mt) {
                int row = wq + mt * 16 + r;
                a[mt][0] = __float_as_uint(Qs[row][kk]);
                a[mt][1] = __float_as_uint(Qs[row + 8][kk]);
                a[mt][2] = __float_as_uint(Qs[row][kk + 4]);
                a[mt][3] = __float_as_uint(Qs[row + 8][kk + 4]);
            }
#pragma unroll
            for (int nt = 0; nt < 2; ++nt) {
                int col = wn + nt * 8 + r;
                bb[nt][0] = __float_as_uint(Ks[col][kk]);
                bb[nt][1] = __float_as_uint(Ks[col][kk + 4]);
            }
#pragma unroll
            for (int mt = 0; mt < 4; ++mt)
#pragma unroll
                for (int nt = 0; nt < 2; ++nt)
                    MMA_TF32(s[mt][nt], a[mt], bb[nt]);
        }
        // Store S fragments to smem
        const int c2 = cq * 2;
#pragma unroll
        for (int mt = 0; mt < 4; ++mt)
#pragma unroll
            for (int nt = 0; nt < 2; ++nt) {
                int row = wq + mt * 16 + r;
                int col = wn + nt * 8 + c2;
                *(float2*)&Ss[row][col]     = make_float2(s[mt][nt][0], s[mt][nt][1]);
                *(float2*)&Ss[row + 8][col] = make_float2(s[mt][nt][2], s[mt][nt][3]);
            }
        __syncthreads();

        // ---- Online softmax: 2 threads per row ----
        {
            int row  = tid >> 1;
            int half = tid & 1;
            int cbase = half * 32;
            float mprev = mrow[row];
            float mloc = -INFINITY;
#pragma unroll
            for (int c = 0; c < 32; ++c) {
                int cc = cbase + c;
                if (maskS[cc]) mloc = fmaxf(mloc, Ss[row][cc]);
            }
            mloc = fmaxf(mloc, __shfl_xor_sync(0xffffffffu, mloc, 1));
            float mnew = fmaxf(mprev, mloc);
            float alpha = 1.f;
            if (mnew != -INFINITY) alpha = __expf(mprev - mnew);
            float lsum = 0.f;
#pragma unroll
            for (int c = 0; c < 32; ++c) {
                int cc = cbase + c;
                float p = 0.f;
                if (maskS[cc]) p = __expf(Ss[row][cc] - mnew);
                lsum += p;
                Ss[row][cc] = tf32r(p);
            }
            lsum += __shfl_xor_sync(0xffffffffu, lsum, 1);
            if (half == 0) {
                mrow[row] = mnew;
                lrow[row] = lrow[row] * alpha + lsum;
                arow[row] = alpha;
            }
        }
        __syncthreads();

        // ---- O = O*alpha + P V  (warp covers 64q x 16d) ----
#pragma unroll
        for (int mt = 0; mt < 4; ++mt) {
            float al0 = arow[wq + mt * 16 + r];
            float al1 = arow[wq + mt * 16 + r + 8];
#pragma unroll
            for (int nt = 0; nt < 2; ++nt) {
                o[mt][nt][0] *= al0; o[mt][nt][1] *= al0;
                o[mt][nt][2] *= al1; o[mt][nt][3] *= al1;
            }
        }
#pragma unroll
        for (int ks = 0; ks < 8; ++ks) {
            const int kk = ks * 8 + cq;
            unsigned a[4][4], bb[2][2];
#pragma unroll
            for (int mt = 0; mt < 4; ++mt) {
                int row = wq + mt * 16 + r;
                a[mt][0] = __float_as_uint(Ss[row][kk]);
                a[mt][1] = __float_as_uint(Ss[row + 8][kk]);
                a[mt][2] = __float_as_uint(Ss[row][kk + 4]);
                a[mt][3] = __float_as_uint(Ss[row + 8][kk + 4]);
            }
#pragma unroll
            for (int nt = 0; nt < 2; ++nt) {
                int col = wn + nt * 8 + r;          // d index
                bb[nt][0] = __float_as_uint(Vs[ks * 8 + cq][col]);
                bb[nt][1] = __float_as_uint(Vs[ks * 8 + cq + 4][col]);
            }
#pragma unroll
            for (int mt = 0; mt < 4; ++mt)
#pragma unroll
                for (int nt = 0; nt < 2; ++nt)
                    MMA_TF32(o[mt][nt], a[mt], bb[nt]);
        }
        __syncthreads();   // protect smem tiles before next iteration
    }

    // Normalize and write out (fully-masked row -> 0)
    const int c2 = cq * 2;
#pragma unroll
    for (int mt = 0; mt < 4; ++mt) {
        int row0 = wq + mt * 16 + r;
        int row1 = row0 + 8;
        float l0 = lrow[row0], l1 = lrow[row1];
        float inv0 = (l0 > 0.f) ? (1.f / l0) : 0.f;
        float inv1 = (l1 > 0.f) ? (1.f / l1) : 0.f;
#pragma unroll
        for (int nt = 0; nt < 2; ++nt) {
            int col = wn + nt * 8 + c2;
            float* d0 = g_att + (size_t)(b * S_ + q0 + row0) * E_ + h * D_ + col;
            float* d1 = g_att + (size_t)(b * S_ + q0 + row1) * E_ + h * D_ + col;
            *(float2*)d0 = make_float2(o[mt][nt][0] * inv0, o[mt][nt][1] * inv0);
            *(float2*)d1 = make_float2(o[mt][nt][2] * inv1, o[mt][nt][3] * inv1);
        }
    }
}

// ---------------------------------------------------------------------------
extern "C" void kernel_launch(void* const* d_in, const int* in_sizes, int n_in,
                              void* d_out, int out_size)
{
    const float* x      = (const float*)d_in[0];
    const int*   mask   = (const int*)d_in[1];
    const float* qkv_w  = (const float*)d_in[2];
    const float* qkv_b  = (const float*)d_in[3];
    const float* proj_w = (const float*)d_in[4];
    const float* proj_b = (const float*)d_in[5];
    float* out = (float*)d_out;

    float *qkv_p, *att_p;
    cudaGetSymbolAddress((void**)&qkv_p, g_qkv);
    cudaGetSymbolAddress((void**)&att_p, g_att);

    // 1) QKV GEMM: [4096,1024] x [3072,1024]^T -> [4096,3072]
    gemm_nt_bias_tf32<<<dim3(3 * E_ / 128, B_ * S_ / 128), 256>>>(
        x, qkv_w, qkv_b, qkv_p, B_ * S_, 3 * E_, E_);

    // 2) Flash attention -> g_att [4096,1024]
    cudaFuncSetAttribute(flash_attn_tf32, cudaFuncAttributeMaxDynamicSharedMemorySize,
                         FA_SMEM_BYTES);
    flash_attn_tf32<<<dim3(S_ / 128, H_, B_), 256, FA_SMEM_BYTES>>>(mask);

    // 3) Proj GEMM: [4096,1024] x [1024,1024]^T -> out [4096,1024]
    gemm_nt_bias_tf32<<<dim3(E_ / 128, B_ * S_ / 128), 256>>>(
        att_p, proj_w, proj_b, out, B_ * S_, E_, E_);
}

// round 5
// speedup vs baseline: 3.2052x; 1.1434x over previous
#include <cuda_runtime.h>
#include <math.h>
#include <stdint.h>

#define B_ 2
#define S_ 2048
#define E_ 1024
#define H_ 16
#define D_ 64

// Scratch (allocation-free rule: __device__ globals)
__device__ float g_qkv[(size_t)B_ * S_ * 3 * E_];  // [B*S][3*E]  (tf32-rounded)
__device__ float g_att[(size_t)B_ * S_ * E_];      // [B*S][E]    (tf32-rounded)
__device__ float g_x [(size_t)B_ * S_ * E_];       // rounded x
__device__ float g_wq[(size_t)3 * E_ * E_];        // rounded qkv_w
__device__ float g_wp[(size_t)E_ * E_];            // rounded proj_w

// ---------------------------------------------------------------------------
// Helpers
// ---------------------------------------------------------------------------
__device__ __forceinline__ float tf32r(float x) {
    float r;
    asm("cvt.rna.tf32.f32 %0, %1;" : "=f"(r) : "f"(x));
    return r;
}
__device__ __forceinline__ uint32_t smem_u32(const void* p) {
    uint32_t a;
    asm("{ .reg .u64 t; cvta.to.shared.u64 t, %1; cvt.u32.u64 %0, t; }"
        : "=r"(a) : "l"(p));
    return a;
}
#define CPA16(dst, src) \
    asm volatile("cp.async.cg.shared.global [%0], [%1], 16;" :: "r"(dst), "l"(src) : "memory")
#define CPA_COMMIT() asm volatile("cp.async.commit_group;" ::: "memory")
#define CPA_WAIT0()  asm volatile("cp.async.wait_group 0;" ::: "memory")
#define CPA_WAIT1()  asm volatile("cp.async.wait_group 1;" ::: "memory")

#define MMA_TF32(d, a, b)                                                     \
    asm volatile(                                                             \
        "mma.sync.aligned.m16n8k8.row.col.f32.tf32.tf32.f32 "                 \
        "{%0,%1,%2,%3},{%4,%5,%6,%7},{%8,%9},{%0,%1,%2,%3};"                  \
        : "+f"((d)[0]), "+f"((d)[1]), "+f"((d)[2]), "+f"((d)[3])              \
        : "r"((a)[0]), "r"((a)[1]), "r"((a)[2]), "r"((a)[3]),                 \
          "r"((b)[0]), "r"((b)[1]))

// ---------------------------------------------------------------------------
// Prep: tf32-round a raw fp32 array into scratch
// ---------------------------------------------------------------------------
__global__ void round_copy(const float* __restrict__ src, float* __restrict__ dst, int n4)
{
    int i = blockIdx.x * blockDim.x + threadIdx.x;
    int stride = gridDim.x * blockDim.x;
    for (; i < n4; i += stride) {
        float4 v = ((const float4*)src)[i];
        v.x = tf32r(v.x); v.y = tf32r(v.y); v.z = tf32r(v.z); v.w = tf32r(v.w);
        ((float4*)dst)[i] = v;
    }
}

// ---------------------------------------------------------------------------
// GEMM: C[m][n] = sum_k A[m][k]*B[n][k] + bias[n].  tf32 MMA, fp32 accum.
// Inputs pre-rounded to tf32. 128x128 tile, BK=32, cp.async double buffer.
// 256 threads = 8 warps (2x4), warp tile 64x32.  do_round: round outputs.
// ---------------------------------------------------------------------------
#define GS_A_STRIDE 36
#define GS_TILE_FLOATS (128 * GS_A_STRIDE)
#define G_SMEM_BYTES (4 * GS_TILE_FLOATS * 4)

__global__ __launch_bounds__(256) void gemm_tf32_pipe(
    const float* __restrict__ A, const float* __restrict__ Bm,
    const float* __restrict__ bias, float* __restrict__ C,
    int M, int N, int K, int do_round)
{
    extern __shared__ float smg[];
    float (*As[2])[GS_A_STRIDE];
    float (*Bs[2])[GS_A_STRIDE];
    As[0] = (float(*)[GS_A_STRIDE])smg;
    As[1] = (float(*)[GS_A_STRIDE])(smg + GS_TILE_FLOATS);
    Bs[0] = (float(*)[GS_A_STRIDE])(smg + 2 * GS_TILE_FLOATS);
    Bs[1] = (float(*)[GS_A_STRIDE])(smg + 3 * GS_TILE_FLOATS);
    const uint32_t sb = smem_u32(smg);

    const int tid  = threadIdx.x;
    const int warp = tid >> 5;
    const int lane = tid & 31;
    const int m0 = blockIdx.y * 128;
    const int n0 = blockIdx.x * 128;
    const int wm = (warp >> 2) * 64;
    const int wn = (warp & 3) * 32;
    const int r  = lane >> 2;
    const int cq = lane & 3;

    // staging: each thread does 4 cp16 per matrix per tile (128 rows x 8 vecs)
    const int srow = tid >> 3;          // 0..31 (x4 -> 128 rows)
    const int svec = tid & 7;           // 0..7 (16B units)

    float acc[4][4][4] = {};

    const int T = K >> 5;

#define GEMM_STAGE(t, buf) do {                                               \
        const int k0_ = (t) << 5;                                             \
        uint32_t abase = sb + ((buf) * GS_TILE_FLOATS) * 4;                   \
        uint32_t bbase = sb + ((2 + (buf)) * GS_TILE_FLOATS) * 4;             \
        _Pragma("unroll")                                                     \
        for (int u = 0; u < 4; ++u) {                                         \
            int row = srow + u * 32;                                          \
            uint32_t da = abase + (row * GS_A_STRIDE + svec * 4) * 4;         \
            CPA16(da, A + (size_t)(m0 + row) * K + k0_ + svec * 4);           \
            uint32_t db = bbase + (row * GS_A_STRIDE + svec * 4) * 4;         \
            CPA16(db, Bm + (size_t)(n0 + row) * K + k0_ + svec * 4);          \
        }                                                                     \
    } while (0)

    GEMM_STAGE(0, 0);
    CPA_COMMIT();

    for (int t = 0; t < T; ++t) {
        const int buf = t & 1;
        if (t + 1 < T) {
            GEMM_STAGE(t + 1, buf ^ 1);
            CPA_COMMIT();
            CPA_WAIT1();
        } else {
            CPA_WAIT0();
        }
        __syncthreads();

        float (*Asb)[GS_A_STRIDE] = As[buf];
        float (*Bsb)[GS_A_STRIDE] = Bs[buf];
#pragma unroll
        for (int ks = 0; ks < 4; ++ks) {
            const int kk = ks * 8 + cq;
            unsigned a[4][4], b[4][2];
#pragma unroll
            for (int mt = 0; mt < 4; ++mt) {
                int row = wm + mt * 16 + r;
                a[mt][0] = __float_as_uint(Asb[row][kk]);
                a[mt][1] = __float_as_uint(Asb[row + 8][kk]);
                a[mt][2] = __float_as_uint(Asb[row][kk + 4]);
                a[mt][3] = __float_as_uint(Asb[row + 8][kk + 4]);
            }
#pragma unroll
            for (int nt = 0; nt < 4; ++nt) {
                int col = wn + nt * 8 + r;
                b[nt][0] = __float_as_uint(Bsb[col][kk]);
                b[nt][1] = __float_as_uint(Bsb[col][kk + 4]);
            }
#pragma unroll
            for (int mt = 0; mt < 4; ++mt)
#pragma unroll
                for (int nt = 0; nt < 4; ++nt)
                    MMA_TF32(acc[mt][nt], a[mt], b[nt]);
        }
        __syncthreads();
    }
#undef GEMM_STAGE

    // Epilogue: bias + (optional tf32 round) + store
    const int c2 = cq * 2;
#pragma unroll
    for (int nt = 0; nt < 4; ++nt) {
        int col = n0 + wn + nt * 8 + c2;
        float b0 = bias[col], b1 = bias[col + 1];
#pragma unroll
        for (int mt = 0; mt < 4; ++mt) {
            int row = m0 + wm + mt * 16 + r;
            float v00 = acc[mt][nt][0] + b0, v01 = acc[mt][nt][1] + b1;
            float v10 = acc[mt][nt][2] + b0, v11 = acc[mt][nt][3] + b1;
            if (do_round) {
                v00 = tf32r(v00); v01 = tf32r(v01);
                v10 = tf32r(v10); v11 = tf32r(v11);
            }
            *(float2*)(C + (size_t)row * N + col)       = make_float2(v00, v01);
            *(float2*)(C + (size_t)(row + 8) * N + col) = make_float2(v10, v11);
        }
    }
}

// ---------------------------------------------------------------------------
// Flash attention: tf32 MMA, cp.async K/V staging, vectorized softmax.
// g_qkv is pre-rounded to tf32.
// ---------------------------------------------------------------------------
#define QS_STRIDE 68
#define FA_WORDS (128 * QS_STRIDE * 2 + 64 * QS_STRIDE * 2 + 3 * 128 + 64)
#define FA_SMEM_BYTES (FA_WORDS * 4)

__global__ __launch_bounds__(256, 2) void flash_attn_tf32(const int* __restrict__ mask)
{
    extern __shared__ float sm[];
    float (*Qs)[QS_STRIDE] = (float(*)[QS_STRIDE])sm;
    float (*Ss)[QS_STRIDE] = (float(*)[QS_STRIDE])(sm + 128 * QS_STRIDE);
    float (*Ks)[QS_STRIDE] = (float(*)[QS_STRIDE])(sm + 2 * 128 * QS_STRIDE);
    float (*Vs)[QS_STRIDE] = (float(*)[QS_STRIDE])(sm + 2 * 128 * QS_STRIDE + 64 * QS_STRIDE);
    float* mrow  = sm + 2 * 128 * QS_STRIDE + 2 * 64 * QS_STRIDE;  // 128
    float* lrow  = mrow + 128;
    float* arow  = lrow + 128;
    float* maskF = arow + 128;                                     // 64

    const uint32_t sb = smem_u32(sm);
    const uint32_t ks_off = (2 * 128 * QS_STRIDE) * 4;
    const uint32_t vs_off = (2 * 128 * QS_STRIDE + 64 * QS_STRIDE) * 4;

    const int tid  = threadIdx.x;
    const int warp = tid >> 5;
    const int lane = tid & 31;
    const int q0 = blockIdx.x * 128;
    const int h  = blockIdx.y;
    const int b  = blockIdx.z;
    const int wq = (warp >> 2) * 64;
    const int wn = (warp & 3) * 16;
    const int r  = lane >> 2;
    const int cq = lane & 3;

    const size_t rowstride = (size_t)3 * E_;
    const float* qbase = g_qkv + (size_t)(b * S_ + q0) * rowstride + h * D_;

    // Load Q (pre-rounded; *0.125 is exact in tf32)
#pragma unroll
    for (int t = 0; t < 8; ++t) {
        int idx = tid + t * 256;
        int row = idx >> 4;
        int vec = idx & 15;
        float4 v = *(const float4*)(qbase + (size_t)row * rowstride + vec * 4);
        Qs[row][vec * 4 + 0] = v.x * 0.125f;
        Qs[row][vec * 4 + 1] = v.y * 0.125f;
        Qs[row][vec * 4 + 2] = v.z * 0.125f;
        Qs[row][vec * 4 + 3] = v.w * 0.125f;
    }
    if (tid < 128) { mrow[tid] = -INFINITY; lrow[tid] = 0.f; }

    float o[4][2][4] = {};
    __syncthreads();

    for (int k0 = 0; k0 < S_; k0 += 64) {
        // Stage K,V via cp.async: 64 rows x 64 floats each = 1024 cp16 per matrix
        {
            const float* kb = g_qkv + (size_t)(b * S_ + k0) * rowstride + E_ + h * D_;
#pragma unroll
            for (int u = 0; u < 4; ++u) {
                int idx = tid + u * 256;      // 0..1023
                int row = idx >> 4;           // 0..63
                int vec = idx & 15;           // 0..15 (16B units)
                uint32_t dk = sb + ks_off + (row * QS_STRIDE + vec * 4) * 4;
                CPA16(dk, kb + (size_t)row * rowstride + vec * 4);
                uint32_t dv = sb + vs_off + (row * QS_STRIDE + vec * 4) * 4;
                CPA16(dv, kb + E_ + (size_t)row * rowstride + vec * 4);
            }
        }
        if (tid < 64) maskF[tid] = mask[b * S_ + k0 + tid] ? 0.f : -INFINITY;
        CPA_COMMIT();
        CPA_WAIT0();
        __syncthreads();

        // ---- S = Q K^T (warp: 64q x 16k) ----
        float s[4][2][4] = {};
#pragma unroll
        for (int ks = 0; ks < 8; ++ks) {
            const int kk = ks * 8 + cq;
            unsigned a[4][4], bb[2][2];
#pragma unroll
            for (int mt = 0; mt < 4; ++mt) {
                int row = wq + mt * 16 + r;
                a[mt][0] = __float_as_uint(Qs[row][kk]);
                a[mt][1] = __float_as_uint(Qs[row + 8][kk]);
                a[mt][2] = __float_as_uint(Qs[row][kk + 4]);
                a[mt][3] = __float_as_uint(Qs[row + 8][kk + 4]);
            }
#pragma unroll
            for (int nt = 0; nt < 2; ++nt) {
                int col = wn + nt * 8 + r;
                bb[nt][0] = __float_as_uint(Ks[col][kk]);
                bb[nt][1] = __float_as_uint(Ks[col][kk + 4]);
            }
#pragma unroll
            for (int mt = 0; mt < 4; ++mt)
#pragma unroll
                for (int nt = 0; nt < 2; ++nt)
                    MMA_TF32(s[mt][nt], a[mt], bb[nt]);
        }
        const int c2 = cq * 2;
#pragma unroll
        for (int mt = 0; mt < 4; ++mt)
#pragma unroll
            for (int nt = 0; nt < 2; ++nt) {
                int row = wq + mt * 16 + r;
                int col = wn + nt * 8 + c2;
                *(float2*)&Ss[row][col]     = make_float2(s[mt][nt][0], s[mt][nt][1]);
                *(float2*)&Ss[row + 8][col] = make_float2(s[mt][nt][2], s[mt][nt][3]);
            }
        __syncthreads();

        // ---- Online softmax: 2 threads/row, float4-vectorized ----
        {
            int row  = tid >> 1;
            int half = tid & 1;
            int cbase = half * 32;
            float sv[32];
#pragma unroll
            for (int v = 0; v < 8; ++v) {
                float4 x4 = *(const float4*)&Ss[row][cbase + v * 4];
                float4 m4 = *(const float4*)&maskF[cbase + v * 4];
                sv[v*4+0] = x4.x + m4.x; sv[v*4+1] = x4.y + m4.y;
                sv[v*4+2] = x4.z + m4.z; sv[v*4+3] = x4.w + m4.w;
            }
            float mprev = mrow[row];
            float mloc = -INFINITY;
#pragma unroll
            for (int c = 0; c < 32; ++c) mloc = fmaxf(mloc, sv[c]);
            mloc = fmaxf(mloc, __shfl_xor_sync(0xffffffffu, mloc, 1));
            float mnew = fmaxf(mprev, mloc);
            float alpha = 1.f;
            float lsum = 0.f;
            if (mnew != -INFINITY) {
                alpha = __expf(mprev - mnew);   // mprev=-inf -> 0
#pragma unroll
                for (int c = 0; c < 32; ++c) {
                    float p = __expf(sv[c] - mnew);  // masked: -inf -> 0
                    lsum += p;
                    sv[c] = tf32r(p);
                }
            } else {
#pragma unroll
                for (int c = 0; c < 32; ++c) sv[c] = 0.f;
            }
#pragma unroll
            for (int v = 0; v < 8; ++v)
                *(float4*)&Ss[row][cbase + v * 4] =
                    make_float4(sv[v*4+0], sv[v*4+1], sv[v*4+2], sv[v*4+3]);
            lsum += __shfl_xor_sync(0xffffffffu, lsum, 1);
            if (half == 0) {
                mrow[row] = mnew;
                lrow[row] = lrow[row] * alpha + lsum;
                arow[row] = alpha;
            }
        }
        __syncthreads();

        // ---- O = O*alpha + P V (warp: 64q x 16d) ----
#pragma unroll
        for (int mt = 0; mt < 4; ++mt) {
            float al0 = arow[wq + mt * 16 + r];
            float al1 = arow[wq + mt * 16 + r + 8];
#pragma unroll
            for (int nt = 0; nt < 2; ++nt) {
                o[mt][nt][0] *= al0; o[mt][nt][1] *= al0;
                o[mt][nt][2] *= al1; o[mt][nt][3] *= al1;
            }
        }
#pragma unroll
        for (int ks = 0; ks < 8; ++ks) {
            const int kk = ks * 8 + cq;
            unsigned a[4][4], bb[2][2];
#pragma unroll
            for (int mt = 0; mt < 4; ++mt) {
                int row = wq + mt * 16 + r;
                a[mt][0] = __float_as_uint(Ss[row][kk]);
                a[mt][1] = __float_as_uint(Ss[row + 8][kk]);
                a[mt][2] = __float_as_uint(Ss[row][kk + 4]);
                a[mt][3] = __float_as_uint(Ss[row + 8][kk + 4]);
            }
#pragma unroll
            for (int nt = 0; nt < 2; ++nt) {
                int col = wn + nt * 8 + r;
                bb[nt][0] = __float_as_uint(Vs[ks * 8 + cq][col]);
                bb[nt][1] = __float_as_uint(Vs[ks * 8 + cq + 4][col]);
            }
#pragma unroll
            for (int mt = 0; mt < 4; ++mt)
#pragma unroll
                for (int nt = 0; nt < 2; ++nt)
                    MMA_TF32(o[mt][nt], a[mt], bb[nt]);
        }
        __syncthreads();
    }

    // Normalize, round to tf32 (A-operand of proj), write out
    const int c2 = cq * 2;
#pragma unroll
    for (int mt = 0; mt < 4; ++mt) {
        int row0 = wq + mt * 16 + r;
        int row1 = row0 + 8;
        float l0 = lrow[row0], l1 = lrow[row1];
        float inv0 = (l0 > 0.f) ? (1.f / l0) : 0.f;
        float inv1 = (l1 > 0.f) ? (1.f / l1) : 0.f;
#pragma unroll
        for (int nt = 0; nt < 2; ++nt) {
            int col = wn + nt * 8 + c2;
            float* d0 = g_att + (size_t)(b * S_ + q0 + row0) * E_ + h * D_ + col;
            float* d1 = g_att + (size_t)(b * S_ + q0 + row1) * E_ + h * D_ + col;
            *(float2*)d0 = make_float2(tf32r(o[mt][nt][0] * inv0), tf32r(o[mt][nt][1] * inv0));
            *(float2*)d1 = make_float2(tf32r(o[mt][nt][2] * inv1), tf32r(o[mt][nt][3] * inv1));
        }
    }
}

// ---------------------------------------------------------------------------
extern "C" void kernel_launch(void* const* d_in, const int* in_sizes, int n_in,
                              void* d_out, int out_size)
{
    const float* x      = (const float*)d_in[0];
    const int*   mask   = (const int*)d_in[1];
    const float* qkv_w  = (const float*)d_in[2];
    const float* qkv_b  = (const float*)d_in[3];
    const float* proj_w = (const float*)d_in[4];
    const float* proj_b = (const float*)d_in[5];
    float* out = (float*)d_out;

    float *qkv_p, *att_p, *x_p, *wq_p, *wp_p;
    cudaGetSymbolAddress((void**)&qkv_p, g_qkv);
    cudaGetSymbolAddress((void**)&att_p, g_att);
    cudaGetSymbolAddress((void**)&x_p,  g_x);
    cudaGetSymbolAddress((void**)&wq_p, g_wq);
    cudaGetSymbolAddress((void**)&wp_p, g_wp);

    cudaFuncSetAttribute(gemm_tf32_pipe, cudaFuncAttributeMaxDynamicSharedMemorySize,
                         G_SMEM_BYTES);
    cudaFuncSetAttribute(flash_attn_tf32, cudaFuncAttributeMaxDynamicSharedMemorySize,
                         FA_SMEM_BYTES);

    // 0) Pre-round inputs to tf32 scratch
    round_copy<<<512, 256>>>(x, x_p, B_ * S_ * E_ / 4);
    round_copy<<<512, 256>>>(qkv_w, wq_p, 3 * E_ * E_ / 4);
    round_copy<<<512, 256>>>(proj_w, wp_p, E_ * E_ / 4);

    // 1) QKV GEMM (round outputs -> g_qkv is tf32)
    gemm_tf32_pipe<<<dim3(3 * E_ / 128, B_ * S_ / 128), 256, G_SMEM_BYTES>>>(
        x_p, wq_p, qkv_b, qkv_p, B_ * S_, 3 * E_, E_, 1);

    // 2) Flash attention -> g_att (tf32-rounded)
    flash_attn_tf32<<<dim3(S_ / 128, H_, B_), 256, FA_SMEM_BYTES>>>(mask);

    // 3) Proj GEMM (no rounding of final output)
    gemm_tf32_pipe<<<dim3(E_ / 128, B_ * S_ / 128), 256, G_SMEM_BYTES>>>(
        att_p, wp_p, proj_b, out, B_ * S_, E_, E_, 0);
}

// round 6
// speedup vs baseline: 3.9231x; 1.2240x over previous
#include <cuda_runtime.h>
#include <math.h>
#include <stdint.h>

#define B_ 2
#define S_ 2048
#define E_ 1024
#define H_ 16
#define D_ 64

// Scratch (allocation-free rule: __device__ globals)
__device__ float g_qkv[(size_t)B_ * S_ * 3 * E_];  // [B*S][3*E]  (tf32-rounded)
__device__ float g_att[(size_t)B_ * S_ * E_];      // [B*S][E]    (tf32-rounded)
__device__ float g_x [(size_t)B_ * S_ * E_];       // rounded x
__device__ float g_wq[(size_t)3 * E_ * E_];        // rounded qkv_w
__device__ float g_wp[(size_t)E_ * E_];            // rounded proj_w

// ---------------------------------------------------------------------------
// Helpers
// ---------------------------------------------------------------------------
__device__ __forceinline__ float tf32r(float x) {
    float r;
    asm("cvt.rna.tf32.f32 %0, %1;" : "=f"(r) : "f"(x));
    return r;
}
__device__ __forceinline__ uint32_t smem_u32(const void* p) {
    uint32_t a;
    asm("{ .reg .u64 t; cvta.to.shared.u64 t, %1; cvt.u32.u64 %0, t; }"
        : "=r"(a) : "l"(p));
    return a;
}
#define CPA16(dst, src) \
    asm volatile("cp.async.cg.shared.global [%0], [%1], 16;" :: "r"(dst), "l"(src) : "memory")
#define CPA_COMMIT() asm volatile("cp.async.commit_group;" ::: "memory")
#define CPA_WAIT0()  asm volatile("cp.async.wait_group 0;" ::: "memory")
#define CPA_WAIT1()  asm volatile("cp.async.wait_group 1;" ::: "memory")

#define MMA_TF32(d, a0, a1, a2, a3, b0, b1)                                   \
    asm volatile(                                                             \
        "mma.sync.aligned.m16n8k8.row.col.f32.tf32.tf32.f32 "                 \
        "{%0,%1,%2,%3},{%4,%5,%6,%7},{%8,%9},{%0,%1,%2,%3};"                  \
        : "+f"((d)[0]), "+f"((d)[1]), "+f"((d)[2]), "+f"((d)[3])              \
        : "r"(a0), "r"(a1), "r"(a2), "r"(a3), "r"(b0), "r"(b1))

// ---------------------------------------------------------------------------
// Prep: tf32-round a raw fp32 array into scratch
// ---------------------------------------------------------------------------
__global__ void round_copy(const float* __restrict__ src, float* __restrict__ dst, int n4)
{
    int i = blockIdx.x * blockDim.x + threadIdx.x;
    int stride = gridDim.x * blockDim.x;
    for (; i < n4; i += stride) {
        float4 v = ((const float4*)src)[i];
        v.x = tf32r(v.x); v.y = tf32r(v.y); v.z = tf32r(v.z); v.w = tf32r(v.w);
        ((float4*)dst)[i] = v;
    }
}

// ---------------------------------------------------------------------------
// GEMM (unchanged from R5): 128x128 tile, BK=32, cp.async double buffer.
// ---------------------------------------------------------------------------
#define GS_A_STRIDE 36
#define GS_TILE_FLOATS (128 * GS_A_STRIDE)
#define G_SMEM_BYTES (4 * GS_TILE_FLOATS * 4)

__global__ __launch_bounds__(256) void gemm_tf32_pipe(
    const float* __restrict__ A, const float* __restrict__ Bm,
    const float* __restrict__ bias, float* __restrict__ C,
    int M, int N, int K, int do_round)
{
    extern __shared__ float smg[];
    float (*As[2])[GS_A_STRIDE];
    float (*Bs[2])[GS_A_STRIDE];
    As[0] = (float(*)[GS_A_STRIDE])smg;
    As[1] = (float(*)[GS_A_STRIDE])(smg + GS_TILE_FLOATS);
    Bs[0] = (float(*)[GS_A_STRIDE])(smg + 2 * GS_TILE_FLOATS);
    Bs[1] = (float(*)[GS_A_STRIDE])(smg + 3 * GS_TILE_FLOATS);
    const uint32_t sb = smem_u32(smg);

    const int tid  = threadIdx.x;
    const int warp = tid >> 5;
    const int lane = tid & 31;
    const int m0 = blockIdx.y * 128;
    const int n0 = blockIdx.x * 128;
    const int wm = (warp >> 2) * 64;
    const int wn = (warp & 3) * 32;
    const int r  = lane >> 2;
    const int cq = lane & 3;

    const int srow = tid >> 3;
    const int svec = tid & 7;

    float acc[4][4][4] = {};
    const int T = K >> 5;

#define GEMM_STAGE(t, buf) do {                                               \
        const int k0_ = (t) << 5;                                             \
        uint32_t abase = sb + ((buf) * GS_TILE_FLOATS) * 4;                   \
        uint32_t bbase = sb + ((2 + (buf)) * GS_TILE_FLOATS) * 4;             \
        _Pragma("unroll")                                                     \
        for (int u = 0; u < 4; ++u) {                                         \
            int row = srow + u * 32;                                          \
            uint32_t da = abase + (row * GS_A_STRIDE + svec * 4) * 4;         \
            CPA16(da, A + (size_t)(m0 + row) * K + k0_ + svec * 4);           \
            uint32_t db = bbase + (row * GS_A_STRIDE + svec * 4) * 4;         \
            CPA16(db, Bm + (size_t)(n0 + row) * K + k0_ + svec * 4);          \
        }                                                                     \
    } while (0)

    GEMM_STAGE(0, 0);
    CPA_COMMIT();

    for (int t = 0; t < T; ++t) {
        const int buf = t & 1;
        if (t + 1 < T) {
            GEMM_STAGE(t + 1, buf ^ 1);
            CPA_COMMIT();
            CPA_WAIT1();
        } else {
            CPA_WAIT0();
        }
        __syncthreads();

        float (*Asb)[GS_A_STRIDE] = As[buf];
        float (*Bsb)[GS_A_STRIDE] = Bs[buf];
#pragma unroll
        for (int ks = 0; ks < 4; ++ks) {
            const int kk = ks * 8 + cq;
            unsigned a[4][4], b[4][2];
#pragma unroll
            for (int mt = 0; mt < 4; ++mt) {
                int row = wm + mt * 16 + r;
                a[mt][0] = __float_as_uint(Asb[row][kk]);
                a[mt][1] = __float_as_uint(Asb[row + 8][kk]);
                a[mt][2] = __float_as_uint(Asb[row][kk + 4]);
                a[mt][3] = __float_as_uint(Asb[row + 8][kk + 4]);
            }
#pragma unroll
            for (int nt = 0; nt < 4; ++nt) {
                int col = wn + nt * 8 + r;
                b[nt][0] = __float_as_uint(Bsb[col][kk]);
                b[nt][1] = __float_as_uint(Bsb[col][kk + 4]);
            }
#pragma unroll
            for (int mt = 0; mt < 4; ++mt)
#pragma unroll
                for (int nt = 0; nt < 4; ++nt)
                    MMA_TF32(acc[mt][nt], a[mt][0], a[mt][1], a[mt][2], a[mt][3],
                             b[nt][0], b[nt][1]);
        }
        __syncthreads();
    }
#undef GEMM_STAGE

    const int c2 = cq * 2;
#pragma unroll
    for (int nt = 0; nt < 4; ++nt) {
        int col = n0 + wn + nt * 8 + c2;
        float b0 = bias[col], b1 = bias[col + 1];
#pragma unroll
        for (int mt = 0; mt < 4; ++mt) {
            int row = m0 + wm + mt * 16 + r;
            float v00 = acc[mt][nt][0] + b0, v01 = acc[mt][nt][1] + b1;
            float v10 = acc[mt][nt][2] + b0, v11 = acc[mt][nt][3] + b1;
            if (do_round) {
                v00 = tf32r(v00); v01 = tf32r(v01);
                v10 = tf32r(v10); v11 = tf32r(v11);
            }
            *(float2*)(C + (size_t)row * N + col)       = make_float2(v00, v01);
            *(float2*)(C + (size_t)(row + 8) * N + col) = make_float2(v10, v11);
        }
    }
}

// ---------------------------------------------------------------------------
// Flash attention v2: FA2-style. 512 threads = 16 warps x 16 query rows.
// Register softmax; S-accumulator reused as PV A-operand via (c0,c2,c1,c3)
// + V row permutation. Q staged once; K/V cp.async double-buffered.
// ---------------------------------------------------------------------------
#define FKV 68
#define FA_Q_FLOATS   (256 * FKV)                 // 17408
#define FA_KV_FLOATS  (64 * FKV)                  // per buffer per matrix
#define FA_OFF_K      FA_Q_FLOATS
#define FA_OFF_V      (FA_Q_FLOATS + 2 * FA_KV_FLOATS)
#define FA_OFF_MASK   (FA_Q_FLOATS + 4 * FA_KV_FLOATS)
#define FA_SMEM_BYTES ((FA_OFF_MASK + 128) * 4)   // 139,776 B

__global__ __launch_bounds__(512) void flash_attn_v2(const int* __restrict__ mask)
{
    extern __shared__ float sm[];
    const uint32_t sb = smem_u32(sm);

    const int tid  = threadIdx.x;
    const int warp = tid >> 5;
    const int lane = tid & 31;
    const int q0 = blockIdx.x * 256;
    const int h  = blockIdx.y;
    const int b  = blockIdx.z;
    const int wq = warp * 16;
    const int r  = lane >> 2;
    const int cq = lane & 3;
    const int qrow = wq + r;

    const size_t rowstride = (size_t)3 * E_;

    // ---- Stage Q (256 x 64) once: 4096 cp16, 8 per thread ----
    {
        const float* qb = g_qkv + (size_t)(b * S_ + q0) * rowstride + h * D_;
#pragma unroll
        for (int u = 0; u < 8; ++u) {
            int idx = tid + u * 512;
            int row = idx >> 4;
            int vec = idx & 15;
            uint32_t dq = sb + (row * FKV + vec * 4) * 4;
            CPA16(dq, qb + (size_t)row * rowstride + vec * 4);
        }
    }

    // ---- K/V stage macro: 64x64 each, 1024 cp16 each, 2 per thread ----
#define FA_STAGE(t, buf) do {                                                 \
        const int k0_ = (t) * 64;                                             \
        const float* kb = g_qkv + (size_t)(b * S_ + k0_) * rowstride + E_ + h * D_; \
        _Pragma("unroll")                                                     \
        for (int u = 0; u < 2; ++u) {                                         \
            int idx = tid + u * 512;                                          \
            int row = idx >> 4;                                               \
            int vec = idx & 15;                                               \
            uint32_t dk = sb + ((FA_OFF_K + (buf) * FA_KV_FLOATS) + row * FKV + vec * 4) * 4; \
            CPA16(dk, kb + (size_t)row * rowstride + vec * 4);                \
            uint32_t dv = sb + ((FA_OFF_V + (buf) * FA_KV_FLOATS) + row * FKV + vec * 4) * 4; \
            CPA16(dv, kb + E_ + (size_t)row * rowstride + vec * 4);           \
        }                                                                     \
        if (tid < 64)                                                         \
            sm[FA_OFF_MASK + (buf) * 64 + tid] =                              \
                mask[b * S_ + k0_ + tid] ? 0.f : -INFINITY;                   \
    } while (0)

    FA_STAGE(0, 0);
    CPA_COMMIT();

    float o[8][4] = {};
    float m0 = -INFINITY, m1 = -INFINITY, l0 = 0.f, l1 = 0.f;

    const int T = S_ / 64;
    for (int t = 0; t < T; ++t) {
        const int buf = t & 1;
        if (t + 1 < T) {
            FA_STAGE(t + 1, buf ^ 1);
            CPA_COMMIT();
            CPA_WAIT1();
        } else {
            CPA_WAIT0();
        }
        __syncthreads();

        const float* Ksb = sm + FA_OFF_K + buf * FA_KV_FLOATS;
        const float* Vsb = sm + FA_OFF_V + buf * FA_KV_FLOATS;
        const float* mkb = sm + FA_OFF_MASK + buf * 64;

        // ---- S = Q K^T : 16q x 64k per warp, acc in registers ----
        float s[8][4] = {};
#pragma unroll
        for (int ks = 0; ks < 8; ++ks) {
            const int kk = ks * 8 + cq;
            unsigned qa0 = __float_as_uint(sm[qrow * FKV + kk]);
            unsigned qa1 = __float_as_uint(sm[(qrow + 8) * FKV + kk]);
            unsigned qa2 = __float_as_uint(sm[qrow * FKV + kk + 4]);
            unsigned qa3 = __float_as_uint(sm[(qrow + 8) * FKV + kk + 4]);
#pragma unroll
            for (int nt = 0; nt < 8; ++nt) {
                unsigned b0 = __float_as_uint(Ksb[(nt * 8 + r) * FKV + kk]);
                unsigned b1 = __float_as_uint(Ksb[(nt * 8 + r) * FKV + kk + 4]);
                MMA_TF32(s[nt], qa0, qa1, qa2, qa3, b0, b1);
            }
        }

        // ---- scale 1/8 + mask (additive 0 / -inf) ----
#pragma unroll
        for (int nt = 0; nt < 8; ++nt) {
            float mk0 = mkb[nt * 8 + 2 * cq];
            float mk1 = mkb[nt * 8 + 2 * cq + 1];
            s[nt][0] = fmaf(s[nt][0], 0.125f, mk0);
            s[nt][1] = fmaf(s[nt][1], 0.125f, mk1);
            s[nt][2] = fmaf(s[nt][2], 0.125f, mk0);
            s[nt][3] = fmaf(s[nt][3], 0.125f, mk1);
        }

        // ---- register online softmax (rows r and r+8) ----
        float mx0 = -INFINITY, mx1 = -INFINITY;
#pragma unroll
        for (int nt = 0; nt < 8; ++nt) {
            mx0 = fmaxf(mx0, fmaxf(s[nt][0], s[nt][1]));
            mx1 = fmaxf(mx1, fmaxf(s[nt][2], s[nt][3]));
        }
        mx0 = fmaxf(mx0, __shfl_xor_sync(0xffffffffu, mx0, 1));
        mx0 = fmaxf(mx0, __shfl_xor_sync(0xffffffffu, mx0, 2));
        mx1 = fmaxf(mx1, __shfl_xor_sync(0xffffffffu, mx1, 1));
        mx1 = fmaxf(mx1, __shfl_xor_sync(0xffffffffu, mx1, 2));

        float mn0 = fmaxf(m0, mx0);
        float mn1 = fmaxf(m1, mx1);
        float al0 = 1.f, al1 = 1.f;
        float ls0 = 0.f, ls1 = 0.f;
        if (mn0 != -INFINITY) {
            al0 = __expf(m0 - mn0);
#pragma unroll
            for (int nt = 0; nt < 8; ++nt) {
                float p0 = __expf(s[nt][0] - mn0);
                float p1 = __expf(s[nt][1] - mn0);
                ls0 += p0 + p1;
                s[nt][0] = tf32r(p0);
                s[nt][1] = tf32r(p1);
            }
        } else {
#pragma unroll
            for (int nt = 0; nt < 8; ++nt) { s[nt][0] = 0.f; s[nt][1] = 0.f; }
        }
        if (mn1 != -INFINITY) {
            al1 = __expf(m1 - mn1);
#pragma unroll
            for (int nt = 0; nt < 8; ++nt) {
                float p2 = __expf(s[nt][2] - mn1);
                float p3 = __expf(s[nt][3] - mn1);
                ls1 += p2 + p3;
                s[nt][2] = tf32r(p2);
                s[nt][3] = tf32r(p3);
            }
        } else {
#pragma unroll
            for (int nt = 0; nt < 8; ++nt) { s[nt][2] = 0.f; s[nt][3] = 0.f; }
        }
        ls0 += __shfl_xor_sync(0xffffffffu, ls0, 1);
        ls0 += __shfl_xor_sync(0xffffffffu, ls0, 2);
        ls1 += __shfl_xor_sync(0xffffffffu, ls1, 1);
        ls1 += __shfl_xor_sync(0xffffffffu, ls1, 2);

        l0 = l0 * al0 + ls0;  m0 = mn0;
        l1 = l1 * al1 + ls1;  m1 = mn1;

#pragma unroll
        for (int nt = 0; nt < 8; ++nt) {
            o[nt][0] *= al0; o[nt][1] *= al0;
            o[nt][2] *= al1; o[nt][3] *= al1;
        }

        // ---- O += P V : A-frag = (c0,c2,c1,c3); V rows (2cq, 2cq+1) ----
#pragma unroll
        for (int ks = 0; ks < 8; ++ks) {
            unsigned pa0 = __float_as_uint(s[ks][0]);
            unsigned pa1 = __float_as_uint(s[ks][2]);
            unsigned pa2 = __float_as_uint(s[ks][1]);
            unsigned pa3 = __float_as_uint(s[ks][3]);
            const float* vrow0 = Vsb + (ks * 8 + 2 * cq) * FKV;
#pragma unroll
            for (int nt = 0; nt < 8; ++nt) {
                unsigned vb0 = __float_as_uint(vrow0[nt * 8 + r]);
                unsigned vb1 = __float_as_uint(vrow0[FKV + nt * 8 + r]);
                MMA_TF32(o[nt], pa0, pa1, pa2, pa3, vb0, vb1);
            }
        }
        __syncthreads();   // protect buf before restage in t+2
    }
#undef FA_STAGE

    // ---- normalize + tf32 round + store ----
    float inv0 = (l0 > 0.f) ? (1.f / l0) : 0.f;
    float inv1 = (l1 > 0.f) ? (1.f / l1) : 0.f;
    float* d0 = g_att + (size_t)(b * S_ + q0 + qrow) * E_ + h * D_;
    float* d1 = g_att + (size_t)(b * S_ + q0 + qrow + 8) * E_ + h * D_;
#pragma unroll
    for (int nt = 0; nt < 8; ++nt) {
        int col = nt * 8 + 2 * cq;
        *(float2*)(d0 + col) = make_float2(tf32r(o[nt][0] * inv0), tf32r(o[nt][1] * inv0));
        *(float2*)(d1 + col) = make_float2(tf32r(o[nt][2] * inv1), tf32r(o[nt][3] * inv1));
    }
}

// ---------------------------------------------------------------------------
extern "C" void kernel_launch(void* const* d_in, const int* in_sizes, int n_in,
                              void* d_out, int out_size)
{
    const float* x      = (const float*)d_in[0];
    const int*   mask   = (const int*)d_in[1];
    const float* qkv_w  = (const float*)d_in[2];
    const float* qkv_b  = (const float*)d_in[3];
    const float* proj_w = (const float*)d_in[4];
    const float* proj_b = (const float*)d_in[5];
    float* out = (float*)d_out;

    float *qkv_p, *att_p, *x_p, *wq_p, *wp_p;
    cudaGetSymbolAddress((void**)&qkv_p, g_qkv);
    cudaGetSymbolAddress((void**)&att_p, g_att);
    cudaGetSymbolAddress((void**)&x_p,  g_x);
    cudaGetSymbolAddress((void**)&wq_p, g_wq);
    cudaGetSymbolAddress((void**)&wp_p, g_wp);

    cudaFuncSetAttribute(gemm_tf32_pipe, cudaFuncAttributeMaxDynamicSharedMemorySize,
                         G_SMEM_BYTES);
    cudaFuncSetAttribute(flash_attn_v2, cudaFuncAttributeMaxDynamicSharedMemorySize,
                         FA_SMEM_BYTES);

    // 0) Pre-round inputs to tf32 scratch
    round_copy<<<512, 256>>>(x, x_p, B_ * S_ * E_ / 4);
    round_copy<<<512, 256>>>(qkv_w, wq_p, 3 * E_ * E_ / 4);
    round_copy<<<512, 256>>>(proj_w, wp_p, E_ * E_ / 4);

    // 1) QKV GEMM (round outputs -> g_qkv is tf32)
    gemm_tf32_pipe<<<dim3(3 * E_ / 128, B_ * S_ / 128), 256, G_SMEM_BYTES>>>(
        x_p, wq_p, qkv_b, qkv_p, B_ * S_, 3 * E_, E_, 1);

    // 2) Flash attention -> g_att (tf32-rounded)
    flash_attn_v2<<<dim3(S_ / 256, H_, B_), 512, FA_SMEM_BYTES>>>(mask);

    // 3) Proj GEMM (no rounding of final output)
    gemm_tf32_pipe<<<dim3(E_ / 128, B_ * S_ / 128), 256, G_SMEM_BYTES>>>(
        att_p, wp_p, proj_b, out, B_ * S_, E_, E_, 0);
}